// round 12
// baseline (speedup 1.0000x reference)
#include <cuda_runtime.h>
#include <math.h>

typedef unsigned long long u64;

static constexpr int Bc   = 8;
static constexpr int NQ   = 512;
static constexpr int NKV  = 512;
static constexpr int Hc   = 16;
static constexpr int Dc   = 256;
static constexpr int MROWS = Bc * NQ;          // 4096
static constexpr int MN   = MROWS * Dc;        // 1048576

// scratch (allocation-free rule: device globals)
__device__ float g_proj[MN];                   // 4 MB
__device__ float g_attn[MN];                   // 4 MB
__device__ float g_scr4[4 * MN];               // 16 MB (gemm partials / attn partial acc)
__device__ float g_pl [4 * MROWS * Hc];        // 1 MB
__device__ float g_ps2[4 * MROWS * Hc];        // 1 MB

// ---------- packed f32x2 helpers ----------
__device__ __forceinline__ u64 pack2(float x, float y) {
    u64 d; asm("mov.b64 %0, {%1, %2};" : "=l"(d) : "f"(x), "f"(y)); return d;
}
__device__ __forceinline__ void unpack2(u64 v, float& x, float& y) {
    asm("mov.b64 {%0, %1}, %2;" : "=f"(x), "=f"(y) : "l"(v));
}
__device__ __forceinline__ u64 fma2(u64 a, u64 b, u64 c) {
    u64 d; asm("fma.rn.f32x2 %0, %1, %2, %3;" : "=l"(d) : "l"(a), "l"(b), "l"(c)); return d;
}
__device__ __forceinline__ float ex2f(float x) {
    float r; asm("ex2.approx.f32 %0, %1;" : "=f"(r) : "f"(x)); return r;
}
__device__ __forceinline__ void cp_async16(void* smem, const void* gptr) {
    unsigned saddr = (unsigned)__cvta_generic_to_shared(smem);
    asm volatile("cp.async.cg.shared.global [%0], [%1], 16;" :: "r"(saddr), "l"(gptr));
}
#define CP_COMMIT()  asm volatile("cp.async.commit_group;" ::: "memory")
#define CP_WAIT(N)   asm volatile("cp.async.wait_group %0;" :: "n"(N) : "memory")

// ============================================================
// GEMM partial: P[z] = A[:, z*K/4:(z+1)*K/4] @ W[:, same]^T  (no bias)
// BM=128, BN=128, BK=16, 256 threads, 8x8 outputs/thread.
// grid (N/128=2, M/128=32, 4) = 256 blocks, 2 blocks/SM.
// ============================================================
__global__ __launch_bounds__(256, 2)
void gemm_partial_kernel(const float* __restrict__ A, const float* __restrict__ W,
                         float* __restrict__ P, int K)
{
    __shared__ float As[2][16][132];   // [buf][k][m]
    __shared__ float Bs[2][16][132];   // [buf][k][n]

    const int t  = threadIdx.x;
    const int tx = t & 15;             // n: 8 outputs at tx*8
    const int ty = t >> 4;             // m: 8 rows at ty*8 (4 pairs)
    const int n0 = blockIdx.x * 128;
    const int m0 = blockIdx.y * 128;
    const int kb = blockIdx.z * (K / 4);

    const int rA = t >> 1;             // 0..127 (row for both A and W tiles)
    const int pA = (t & 1) * 8;        // k base 0/8

    u64 acc[4][8];
#pragma unroll
    for (int i = 0; i < 4; i++)
#pragma unroll
        for (int j = 0; j < 8; j++) acc[i][j] = pack2(0.f, 0.f);

    const float* aptr = A + (size_t)(m0 + rA) * K + kb + pA;
    const float* wptr = W + (size_t)(n0 + rA) * K + kb + pA;

    float4 pa0 = *reinterpret_cast<const float4*>(aptr);
    float4 pa1 = *reinterpret_cast<const float4*>(aptr + 4);
    float4 pw0 = *reinterpret_cast<const float4*>(wptr);
    float4 pw1 = *reinterpret_cast<const float4*>(wptr + 4);

    // store tile 0
    As[0][pA + 0][rA] = pa0.x; As[0][pA + 1][rA] = pa0.y;
    As[0][pA + 2][rA] = pa0.z; As[0][pA + 3][rA] = pa0.w;
    As[0][pA + 4][rA] = pa1.x; As[0][pA + 5][rA] = pa1.y;
    As[0][pA + 6][rA] = pa1.z; As[0][pA + 7][rA] = pa1.w;
    Bs[0][pA + 0][rA] = pw0.x; Bs[0][pA + 1][rA] = pw0.y;
    Bs[0][pA + 2][rA] = pw0.z; Bs[0][pA + 3][rA] = pw0.w;
    Bs[0][pA + 4][rA] = pw1.x; Bs[0][pA + 5][rA] = pw1.y;
    Bs[0][pA + 6][rA] = pw1.z; Bs[0][pA + 7][rA] = pw1.w;

    // load tile 1
    pa0 = *reinterpret_cast<const float4*>(aptr + 16);
    pa1 = *reinterpret_cast<const float4*>(aptr + 20);
    pw0 = *reinterpret_cast<const float4*>(wptr + 16);
    pw1 = *reinterpret_cast<const float4*>(wptr + 20);
    __syncthreads();

    const int NT = (K / 4) / 16;       // 4
    for (int i = 0; i < NT; i++) {
        const int buf = i & 1;
        if (i < NT - 1) {
            As[buf ^ 1][pA + 0][rA] = pa0.x; As[buf ^ 1][pA + 1][rA] = pa0.y;
            As[buf ^ 1][pA + 2][rA] = pa0.z; As[buf ^ 1][pA + 3][rA] = pa0.w;
            As[buf ^ 1][pA + 4][rA] = pa1.x; As[buf ^ 1][pA + 5][rA] = pa1.y;
            As[buf ^ 1][pA + 6][rA] = pa1.z; As[buf ^ 1][pA + 7][rA] = pa1.w;
            Bs[buf ^ 1][pA + 0][rA] = pw0.x; Bs[buf ^ 1][pA + 1][rA] = pw0.y;
            Bs[buf ^ 1][pA + 2][rA] = pw0.z; Bs[buf ^ 1][pA + 3][rA] = pw0.w;
            Bs[buf ^ 1][pA + 4][rA] = pw1.x; Bs[buf ^ 1][pA + 5][rA] = pw1.y;
            Bs[buf ^ 1][pA + 6][rA] = pw1.z; Bs[buf ^ 1][pA + 7][rA] = pw1.w;
        }
        if (i < NT - 2) {
            pa0 = *reinterpret_cast<const float4*>(aptr + (i + 2) * 16);
            pa1 = *reinterpret_cast<const float4*>(aptr + (i + 2) * 16 + 4);
            pw0 = *reinterpret_cast<const float4*>(wptr + (i + 2) * 16);
            pw1 = *reinterpret_cast<const float4*>(wptr + (i + 2) * 16 + 4);
        }
#pragma unroll
        for (int kk = 0; kk < 16; kk++) {
            const u64* a2 = reinterpret_cast<const u64*>(&As[buf][kk][ty * 8]);
            u64 am[4] = {a2[0], a2[1], a2[2], a2[3]};
            float4 b0 = *reinterpret_cast<const float4*>(&Bs[buf][kk][tx * 8]);
            float4 b1 = *reinterpret_cast<const float4*>(&Bs[buf][kk][tx * 8 + 4]);
            u64 bd[8] = {pack2(b0.x, b0.x), pack2(b0.y, b0.y),
                         pack2(b0.z, b0.z), pack2(b0.w, b0.w),
                         pack2(b1.x, b1.x), pack2(b1.y, b1.y),
                         pack2(b1.z, b1.z), pack2(b1.w, b1.w)};
#pragma unroll
            for (int i2 = 0; i2 < 4; i2++)
#pragma unroll
                for (int j = 0; j < 8; j++)
                    acc[i2][j] = fma2(am[i2], bd[j], acc[i2][j]);
        }
        __syncthreads();
    }

    float* pb = P + (size_t)blockIdx.z * MN;
#pragma unroll
    for (int i = 0; i < 4; i++) {
        float lo[8], hi[8];
#pragma unroll
        for (int j = 0; j < 8; j++) unpack2(acc[i][j], lo[j], hi[j]);
        float* r0 = pb + (size_t)(m0 + ty * 8 + 2 * i) * Dc + n0 + tx * 8;
        float* r1 = r0 + Dc;
        *reinterpret_cast<float4*>(r0)     = make_float4(lo[0], lo[1], lo[2], lo[3]);
        *reinterpret_cast<float4*>(r0 + 4) = make_float4(lo[4], lo[5], lo[6], lo[7]);
        *reinterpret_cast<float4*>(r1)     = make_float4(hi[0], hi[1], hi[2], hi[3]);
        *reinterpret_cast<float4*>(r1 + 4) = make_float4(hi[4], hi[5], hi[6], hi[7]);
    }
}

// C = sum_z P[z] + bias     (262144 float4, grid 1024 x 256)
__global__ __launch_bounds__(256)
void gemm_combine_kernel(const float* __restrict__ P, const float* __restrict__ bias,
                         float* __restrict__ C)
{
    int gid = blockIdx.x * 256 + threadIdx.x;
    float4 s = reinterpret_cast<const float4*>(bias)[gid & 63];
#pragma unroll
    for (int z = 0; z < 4; z++) {
        float4 a = reinterpret_cast<const float4*>(P + (size_t)z * MN)[gid];
        s.x += a.x; s.y += a.y; s.z += a.z; s.w += a.w;
    }
    reinterpret_cast<float4*>(C)[gid] = s;
}

// ============================================================
// attn partial: grid (16, 8, 4) = 512 blocks, 128 threads, 3 blocks/SM.
// Block (qt, b, z): 32 queries x k range [z*128, z*128+128).
// Threads: 8 qgroups x 16 heads, qpt=4. cp.async double-buffered smem
// for features / messages / adjacency (R11-validated inner loop).
// Writes unscaled acc + l + s2 partials to gmem.
// ============================================================
static constexpr int KC = 8;
static constexpr int FEAT_B = KC * Dc;    // 2048 floats
static constexpr int MSG_B  = 32 * 132;   // 4224 floats
static constexpr int ADJ_B  = 32 * 8;     // 256 ints
static constexpr int SMEM_ATTN = (2 * (FEAT_B + MSG_B) + 2 * ADJ_B) * 4;  // 52224 B

__global__ __launch_bounds__(128, 3)
void attn_partial_kernel(const float* __restrict__ messages, const int* __restrict__ adj,
                         float* __restrict__ pacc, float* __restrict__ pl,
                         float* __restrict__ ps2)
{
    extern __shared__ __align__(16) float smemF[];
    float* featS = smemF;                          // [2][FEAT_B]
    float* msgS  = smemF + 2 * FEAT_B;             // [2][MSG_B]
    int*   adjS  = (int*)(smemF + 2 * (FEAT_B + MSG_B));  // [2][ADJ_B]

    const int t  = threadIdx.x;
    const int h  = t & 15;
    const int qg = t >> 4;                 // 0..7
    const int b  = blockIdx.y;
    const int z  = blockIdx.z;
    const int qb0 = blockIdx.x * 32;
    const int qbase = qb0 + qg * 4;
    const int kb = z * (NKV / 4);          // 128-k range

    const float4* msgG  = (const float4*)(messages + (size_t)(b * NQ + qb0) * NKV * Hc);
    const int*    adjG  = adj + (size_t)(b * NQ + qb0) * NKV;
    const float4* proj4 = (const float4*)(g_proj + (size_t)b * NKV * Dc);

    float l[4]  = {0.f, 0.f, 0.f, 0.f};
    float s2[4] = {0.f, 0.f, 0.f, 0.f};
    u64 acc[4][8];
#pragma unroll
    for (int qi = 0; qi < 4; qi++)
#pragma unroll
        for (int j = 0; j < 8; j++) acc[qi][j] = pack2(0.f, 0.f);

    auto load_chunk = [&](int c, int buf) {
        const int k0 = kb + c * KC;
        float* fb = featS + buf * FEAT_B;
#pragma unroll
        for (int i = 0; i < 4; i++) {          // 512 f4 / 128 threads
            int lin = t + i * 128;
            int kk = lin >> 6, g = lin & 63;
            int hh = g >> 2, j = g & 3;
            int dstf4 = j * (KC * 16) + kk * 16 + (hh ^ (2 * j));
            cp_async16(fb + dstf4 * 4, &proj4[(size_t)(k0 + kk) * 64 + g]);
        }
        float* mb = msgS + buf * MSG_B;
#pragma unroll
        for (int i = 0; i < 8; i++) {          // 1024 f4 / 128 threads
            int lin = t + i * 128;
            int q = lin >> 5, g32 = lin & 31;
            cp_async16(mb + q * 132 + g32 * 4,
                       &msgG[((size_t)q * NKV + k0 + (g32 >> 2)) * 4 + (g32 & 3)]);
        }
        if (t < 64) {                          // 64 int4 granules
            int q = t >> 1, hf = t & 1;
            cp_async16(adjS + buf * ADJ_B + q * 8 + hf * 4,
                       adjG + (size_t)q * NKV + k0 + hf * 4);
        }
        CP_COMMIT();
    };

    const float L2E = 1.4426950408889634f;
    const int NCI = (NKV / 4) / KC;   // 16 chunks
    load_chunk(0, 0);

    for (int ci = 0; ci < NCI; ci++) {
        const int buf = ci & 1;
        CP_WAIT(0);
        __syncthreads();
        if (ci + 1 < NCI) load_chunk(ci + 1, buf ^ 1);

        const float* fb = featS + buf * FEAT_B;
        const float* mb = msgS + buf * MSG_B;
        const int*   ab = adjS + buf * ADJ_B;

#pragma unroll
        for (int g = 0; g < 2; g++) {
            int4 av[4];
#pragma unroll
            for (int qi = 0; qi < 4; qi++)
                av[qi] = *reinterpret_cast<const int4*>(&ab[(qg * 4 + qi) * 8 + g * 4]);
#pragma unroll
            for (int u = 0; u < 4; u++) {
                const int kk = g * 4 + u;
                u64 f[8];
#pragma unroll
                for (int j = 0; j < 4; j++) {
                    float4 fv = *reinterpret_cast<const float4*>(
                        &fb[(j * (KC * 16) + kk * 16 + (h ^ (2 * j))) * 4]);
                    f[2 * j]     = pack2(fv.x, fv.y);
                    f[2 * j + 1] = pack2(fv.z, fv.w);
                }
#pragma unroll
                for (int qi = 0; qi < 4; qi++) {
                    float mv = mb[(qg * 4 + qi) * 132 + kk * 16 + h];
                    int a = (&av[qi].x)[u];
                    float lg = fmaf(mv, L2E, (a > 0) ? 0.f : -2e9f);
                    float p = ex2f(lg);
                    l[qi] += p;
                    s2[qi] = fmaf(p, p, s2[qi]);
                    u64 pp = pack2(p, p);
#pragma unroll
                    for (int j = 0; j < 8; j++)
                        acc[qi][j] = fma2(pp, f[j], acc[qi][j]);
                }
            }
        }
    }

    // write unscaled partials
#pragma unroll
    for (int qi = 0; qi < 4; qi++) {
        int row = b * NQ + qbase + qi;
        float* pr = pacc + ((size_t)z * MROWS + row) * Dc + h * 16;
        float v[16];
#pragma unroll
        for (int j = 0; j < 8; j++) unpack2(acc[qi][j], v[2 * j], v[2 * j + 1]);
#pragma unroll
        for (int j = 0; j < 4; j++)
            *reinterpret_cast<float4*>(pr + 4 * j) =
                make_float4(v[4*j], v[4*j+1], v[4*j+2], v[4*j+3]);
        pl [((size_t)z * MROWS + row) * Hc + h] = l[qi];
        ps2[((size_t)z * MROWS + row) * Hc + h] = s2[qi];
    }
}

// out[row][c] = (sum_z acc) * sqrt(sum s2) / (sum l)^2
__global__ __launch_bounds__(256)
void attn_combine_kernel(const float* __restrict__ pacc, const float* __restrict__ pl,
                         const float* __restrict__ ps2, float* __restrict__ outp)
{
    int gid = blockIdx.x * 256 + threadIdx.x;   // 262144 total
    int row = gid >> 6;
    int c4  = gid & 63;
    int h   = c4 >> 2;
    float4 v = make_float4(0.f, 0.f, 0.f, 0.f);
    float ls = 0.f, ss = 0.f;
#pragma unroll
    for (int z = 0; z < 4; z++) {
        float4 a = reinterpret_cast<const float4*>(
            pacc + ((size_t)z * MROWS + row) * Dc)[c4];
        v.x += a.x; v.y += a.y; v.z += a.z; v.w += a.w;
        ls += pl [((size_t)z * MROWS + row) * Hc + h];
        ss += ps2[((size_t)z * MROWS + row) * Hc + h];
    }
    float w = sqrtf(ss) / (ls * ls);
    reinterpret_cast<float4*>(outp + (size_t)row * Dc)[c4] =
        make_float4(v.x * w, v.y * w, v.z * w, v.w * w);
}

// ============================================================
extern "C" void kernel_launch(void* const* d_in, const int* in_sizes, int n_in,
                              void* d_out, int out_size)
{
    const float* v_inv    = (const float*)d_in[0];
    const float* messages = (const float*)d_in[1];
    const int*   adjm     = (const int*)d_in[2];
    const float* W_in     = (const float*)d_in[3];
    const float* b_in     = (const float*)d_in[4];
    const float* W_out    = (const float*)d_in[5];
    const float* b_out    = (const float*)d_in[6];
    float* out = (float*)d_out;

    float *p_proj = nullptr, *p_attn = nullptr, *p_scr = nullptr, *p_l = nullptr, *p_s2 = nullptr;
    cudaGetSymbolAddress((void**)&p_proj, g_proj);
    cudaGetSymbolAddress((void**)&p_attn, g_attn);
    cudaGetSymbolAddress((void**)&p_scr,  g_scr4);
    cudaGetSymbolAddress((void**)&p_l,    g_pl);
    cudaGetSymbolAddress((void**)&p_s2,   g_ps2);

    cudaFuncSetAttribute(attn_partial_kernel,
                         cudaFuncAttributeMaxDynamicSharedMemorySize, SMEM_ATTN);

    // 1) proj partials + combine:  g_proj = v_inv @ W_in^T + b_in
    gemm_partial_kernel<<<dim3(2, 32, 4), 256>>>(v_inv, W_in, p_scr, Dc);
    gemm_combine_kernel<<<1024, 256>>>(p_scr, b_in, p_proj);

    // 2) attention partials + combine -> g_attn
    attn_partial_kernel<<<dim3(16, 8, 4), 128, SMEM_ATTN>>>(messages, adjm, p_scr, p_l, p_s2);
    attn_combine_kernel<<<1024, 256>>>(p_scr, p_l, p_s2, p_attn);

    // 3) out partials + combine:  out = g_attn @ W_out^T + b_out
    gemm_partial_kernel<<<dim3(2, 32, 4), 256>>>(p_attn, W_out, p_scr, Dc);
    gemm_combine_kernel<<<1024, 256>>>(p_scr, b_out, out);
}

// round 13
// speedup vs baseline: 1.1557x; 1.1557x over previous
#include <cuda_runtime.h>
#include <math.h>

typedef unsigned long long u64;

static constexpr int Bc   = 8;
static constexpr int NQ   = 512;
static constexpr int NKV  = 512;
static constexpr int Hc   = 16;
static constexpr int Dc   = 256;

// scratch (allocation-free rule: device globals)
__device__ float g_proj[Bc * NKV * Dc];   // 4 MB
__device__ float g_attn[Bc * NQ  * Dc];   // 4 MB

// ---------- packed f32x2 helpers ----------
__device__ __forceinline__ u64 pack2(float x, float y) {
    u64 d; asm("mov.b64 %0, {%1, %2};" : "=l"(d) : "f"(x), "f"(y)); return d;
}
__device__ __forceinline__ void unpack2(u64 v, float& x, float& y) {
    asm("mov.b64 {%0, %1}, %2;" : "=f"(x), "=f"(y) : "l"(v));
}
__device__ __forceinline__ u64 fma2(u64 a, u64 b, u64 c) {
    u64 d; asm("fma.rn.f32x2 %0, %1, %2, %3;" : "=l"(d) : "l"(a), "l"(b), "l"(c)); return d;
}
__device__ __forceinline__ float ex2f(float x) {
    float r; asm("ex2.approx.f32 %0, %1;" : "=f"(r) : "f"(x)); return r;
}
__device__ __forceinline__ void cp_async16(void* smem, const void* gptr) {
    unsigned saddr = (unsigned)__cvta_generic_to_shared(smem);
    asm volatile("cp.async.cg.shared.global [%0], [%1], 16;" :: "r"(saddr), "l"(gptr));
}
#define CP_COMMIT()  asm volatile("cp.async.commit_group;" ::: "memory")
#define CP_WAIT(N)   asm volatile("cp.async.wait_group %0;" :: "n"(N) : "memory")

__device__ __forceinline__ void barx128(int id) {
    asm volatile("bar.sync %0, 128;" :: "r"(id) : "memory");
}

// ============================================================
// GEMM: C[m,n] = sum_k A[m,k] * W[n,k] + bias[n]
// BM=128, BN=64, BK=16, 512 threads. Double-buffered smem, one
// sync/tile, LDG two tiles ahead. A m-pairs read directly as u64
// (no repack MOVs) -> inner kk = 2 LDS.128 + 4 dup + 8 fma2.
// ============================================================
__global__ __launch_bounds__(512)
void gemm_bias_kernel(const float* __restrict__ A, const float* __restrict__ W,
                      const float* __restrict__ bias, float* __restrict__ C,
                      int M, int N, int K)
{
    __shared__ float As[2][16][132];   // [buf][k][m]
    __shared__ float Bs[2][16][68];    // [buf][k][n]

    const int t  = threadIdx.x;
    const int tx = t & 15;             // n: 4 outputs at tx*4
    const int ty = t >> 4;             // m: 4 rows at ty*4 (2 u64 pairs)
    const int m0 = blockIdx.y * 128;
    const int n0 = blockIdx.x * 64;

    const int rA = t >> 2;             // 0..127
    const int pA = (t & 3) * 4;        // k base 0,4,8,12
    const bool wact = (t < 256);
    const int rW = (t >> 2) & 63;      // 0..63
    const int pW = (t & 3) * 4;

    u64 acc[2][4];
#pragma unroll
    for (int i = 0; i < 2; i++)
#pragma unroll
        for (int j = 0; j < 4; j++) acc[i][j] = pack2(0.f, 0.f);

    const float* aptr = A + (size_t)(m0 + rA) * K + pA;
    const float* wptr = W + (size_t)(n0 + rW) * K + pW;

    float4 a0 = *reinterpret_cast<const float4*>(aptr);
    float4 w0 = wact ? *reinterpret_cast<const float4*>(wptr) : make_float4(0,0,0,0);

    As[0][pA + 0][rA] = a0.x; As[0][pA + 1][rA] = a0.y;
    As[0][pA + 2][rA] = a0.z; As[0][pA + 3][rA] = a0.w;
    if (wact) {
        Bs[0][pW + 0][rW] = w0.x; Bs[0][pW + 1][rW] = w0.y;
        Bs[0][pW + 2][rW] = w0.z; Bs[0][pW + 3][rW] = w0.w;
    }
    a0 = *reinterpret_cast<const float4*>(aptr + 16);
    if (wact) w0 = *reinterpret_cast<const float4*>(wptr + 16);
    __syncthreads();

    const int NT = K / 16;   // 16
    for (int i = 0; i < NT; i++) {
        const int buf = i & 1;
        if (i < NT - 1) {
            As[buf ^ 1][pA + 0][rA] = a0.x; As[buf ^ 1][pA + 1][rA] = a0.y;
            As[buf ^ 1][pA + 2][rA] = a0.z; As[buf ^ 1][pA + 3][rA] = a0.w;
            if (wact) {
                Bs[buf ^ 1][pW + 0][rW] = w0.x; Bs[buf ^ 1][pW + 1][rW] = w0.y;
                Bs[buf ^ 1][pW + 2][rW] = w0.z; Bs[buf ^ 1][pW + 3][rW] = w0.w;
            }
        }
        if (i < NT - 2) {
            a0 = *reinterpret_cast<const float4*>(aptr + (i + 2) * 16);
            if (wact) w0 = *reinterpret_cast<const float4*>(wptr + (i + 2) * 16);
        }
#pragma unroll
        for (int kk = 0; kk < 16; kk++) {
            const u64* a2 = reinterpret_cast<const u64*>(&As[buf][kk][ty * 4]);
            u64 am0 = a2[0], am1 = a2[1];
            float4 bv = *reinterpret_cast<const float4*>(&Bs[buf][kk][tx * 4]);
            u64 bd[4] = {pack2(bv.x, bv.x), pack2(bv.y, bv.y),
                         pack2(bv.z, bv.z), pack2(bv.w, bv.w)};
#pragma unroll
            for (int j = 0; j < 4; j++) {
                acc[0][j] = fma2(am0, bd[j], acc[0][j]);
                acc[1][j] = fma2(am1, bd[j], acc[1][j]);
            }
        }
        __syncthreads();
    }

    float4 bv = *reinterpret_cast<const float4*>(bias + n0 + tx * 4);
#pragma unroll
    for (int i = 0; i < 2; i++) {
        float lo[4], hi[4];
#pragma unroll
        for (int j = 0; j < 4; j++) unpack2(acc[i][j], lo[j], hi[j]);
        float4 o0 = make_float4(lo[0] + bv.x, lo[1] + bv.y, lo[2] + bv.z, lo[3] + bv.w);
        float4 o1 = make_float4(hi[0] + bv.x, hi[1] + bv.y, hi[2] + bv.z, hi[3] + bv.w);
        *reinterpret_cast<float4*>(C + (size_t)(m0 + ty * 4 + 2 * i) * N + n0 + tx * 4) = o0;
        *reinterpret_cast<float4*>(C + (size_t)(m0 + ty * 4 + 2 * i + 1) * N + n0 + tx * 4) = o1;
    }
}

// ============================================================
// Fused masked softmax + per-head aggregation + L2-norm rescale.
// 512 threads = 4 k-split quarters x (8 qgroups x 16 heads), qpt=4.
// *** 4-stage cp.async pipeline (KC=4, wait_group(2)) ***: 3 chunks
// in flight per quarter so the DRAM stream never stalls on compute.
// ============================================================
static constexpr int KCq   = 4;
static constexpr int NSTG  = 4;
static constexpr int FEAT_B = KCq * Dc;     // 1024 floats
static constexpr int MSG_W  = 68;           // padded msg row (64 + 4)
static constexpr int MSG_B  = 32 * MSG_W;   // 2176 floats
static constexpr int ADJ_B  = 32 * KCq;     // 128 ints
static constexpr int FEAT_T = 4 * NSTG * FEAT_B;   // 16384
static constexpr int MSG_T  = 4 * NSTG * MSG_B;    // 34816
static constexpr int ADJ_T  = 4 * NSTG * ADJ_B;    // 2048
static constexpr int SMEM_ATTN = (FEAT_T + MSG_T + ADJ_T) * 4;  // 212992 B

__global__ __launch_bounds__(512)
void attn_kernel(const float* __restrict__ messages, const int* __restrict__ adj,
                 float* __restrict__ outp)
{
    extern __shared__ __align__(16) float smemF[];
    float* featA = smemF;                        // [4][NSTG][FEAT_B]
    float* msgA  = smemF + FEAT_T;               // [4][NSTG][MSG_B]
    int*   adjA  = (int*)(smemF + FEAT_T + MSG_T);  // [4][NSTG][ADJ_B]

    const int t  = threadIdx.x;
    const int quarter = t >> 7;
    const int lt = t & 127;
    const int h  = lt & 15;
    const int qg = lt >> 4;                // 0..7
    const int b  = blockIdx.y;
    const int qb0 = blockIdx.x * 32;
    const int qbase = qb0 + qg * 4;

    const float4* msgG  = (const float4*)(messages + (size_t)(b * NQ + qb0) * NKV * Hc);
    const int*    adjG  = adj + (size_t)(b * NQ + qb0) * NKV;
    const float4* proj4 = (const float4*)(g_proj + (size_t)b * NKV * Dc);

    float l[4]  = {0.f, 0.f, 0.f, 0.f};
    float s2[4] = {0.f, 0.f, 0.f, 0.f};
    u64 acc[4][8];
#pragma unroll
    for (int qi = 0; qi < 4; qi++)
#pragma unroll
        for (int j = 0; j < 8; j++) acc[qi][j] = pack2(0.f, 0.f);

    // stage loader: chunk c (4 k-rows) into stage slot s of this quarter
    auto load_stage = [&](int c, int s) {
        const int k0 = c * KCq;
        float* fb = featA + (quarter * NSTG + s) * FEAT_B;
#pragma unroll
        for (int i = 0; i < 2; i++) {          // 256 f4 / 128 threads
            int lin = lt + i * 128;
            int kk = lin >> 6, g = lin & 63;
            int hh = g >> 2, j = g & 3;
            int dstf4 = j * (KCq * 16) + kk * 16 + (hh ^ (2 * j));
            cp_async16(fb + dstf4 * 4, &proj4[(size_t)(k0 + kk) * 64 + g]);
        }
        float* mb = msgA + (quarter * NSTG + s) * MSG_B;
#pragma unroll
        for (int i = 0; i < 4; i++) {          // 512 f4 / 128 threads
            int lin = lt + i * 128;
            int q = lin >> 4, g16 = lin & 15;  // 16 f4 per q-row per chunk
            cp_async16(mb + q * MSG_W + g16 * 4,
                       &msgG[((size_t)q * NKV + k0 + (g16 >> 2)) * 4 + (g16 & 3)]);
        }
        if (lt < 32) {                          // 32 int4 granules
            cp_async16(adjA + (quarter * NSTG + s) * ADJ_B + lt * 4,
                       adjG + (size_t)lt * NKV + k0);
        }
        CP_COMMIT();
    };

    const float L2E = 1.4426950408889634f;
    const int NCI = NKV / KCq / 4;   // 32 chunks per quarter

    load_stage(quarter, 0);
    load_stage(4 + quarter, 1);
    load_stage(8 + quarter, 2);

    for (int ci = 0; ci < NCI; ci++) {
        const int s = ci & (NSTG - 1);
        CP_WAIT(2);                  // stage ci complete (2 newer may be in flight)
        barx128(quarter + 1);        // all 4 warps past last use of slot (ci+3)&3
        if (ci + 3 < NCI) load_stage(4 * (ci + 3) + quarter, (ci + 3) & (NSTG - 1));
        else              CP_COMMIT();   // keep group accounting aligned

        const float* fb = featA + (quarter * NSTG + s) * FEAT_B;
        const float* mb = msgA  + (quarter * NSTG + s) * MSG_B;
        const int*   ab = adjA  + (quarter * NSTG + s) * ADJ_B;

        int4 av[4];
#pragma unroll
        for (int qi = 0; qi < 4; qi++)
            av[qi] = *reinterpret_cast<const int4*>(&ab[(qg * 4 + qi) * 4]);
#pragma unroll
        for (int u = 0; u < 4; u++) {
            const int kk = u;
            u64 f[8];
#pragma unroll
            for (int j = 0; j < 4; j++) {
                float4 fv = *reinterpret_cast<const float4*>(
                    &fb[(j * (KCq * 16) + kk * 16 + (h ^ (2 * j))) * 4]);
                f[2 * j]     = pack2(fv.x, fv.y);
                f[2 * j + 1] = pack2(fv.z, fv.w);
            }
#pragma unroll
            for (int qi = 0; qi < 4; qi++) {
                float mv = mb[(qg * 4 + qi) * MSG_W + kk * 16 + h];
                int a = (&av[qi].x)[u];
                float lg = fmaf(mv, L2E, (a > 0) ? 0.f : -2e9f);
                float p = ex2f(lg);
                l[qi] += p;
                s2[qi] = fmaf(p, p, s2[qi]);
                u64 pp = pack2(p, p);
#pragma unroll
                for (int j = 0; j < 8; j++)
                    acc[qi][j] = fma2(pp, f[j], acc[qi][j]);
            }
        }
    }

    // ---- combine quarters (overlay redS on msgA region) ----
    __syncthreads();
    float* redS = msgA;    // 3 * 128 * 73 = 28032 floats <= MSG_T
    if (quarter > 0) {
        float* s = redS + ((size_t)(quarter - 1) * 128 + lt) * 73;
#pragma unroll
        for (int qi = 0; qi < 4; qi++) {
#pragma unroll
            for (int j = 0; j < 8; j++)
                unpack2(acc[qi][j], s[qi * 18 + 2 * j], s[qi * 18 + 2 * j + 1]);
            s[qi * 18 + 16] = l[qi];
            s[qi * 18 + 17] = s2[qi];
        }
    }
    __syncthreads();
    if (quarter == 0) {
#pragma unroll
        for (int qi = 0; qi < 4; qi++) {
            float v[16];
#pragma unroll
            for (int j = 0; j < 8; j++) unpack2(acc[qi][j], v[2 * j], v[2 * j + 1]);
            float lsum = l[qi], s2sum = s2[qi];
#pragma unroll
            for (int r = 0; r < 3; r++) {
                const float* s = redS + ((size_t)r * 128 + lt) * 73 + qi * 18;
#pragma unroll
                for (int j = 0; j < 16; j++) v[j] += s[j];
                lsum  += s[16];
                s2sum += s[17];
            }
            float w = sqrtf(s2sum) / (lsum * lsum);
            float* o = outp + (size_t)(b * NQ + qbase + qi) * Dc + h * 16;
#pragma unroll
            for (int j = 0; j < 4; j++) {
                float4 ov = make_float4(v[4*j] * w, v[4*j+1] * w, v[4*j+2] * w, v[4*j+3] * w);
                *reinterpret_cast<float4*>(o + 4 * j) = ov;
            }
        }
    }
}

// ============================================================
extern "C" void kernel_launch(void* const* d_in, const int* in_sizes, int n_in,
                              void* d_out, int out_size)
{
    const float* v_inv    = (const float*)d_in[0];
    const float* messages = (const float*)d_in[1];
    const int*   adjm     = (const int*)d_in[2];
    const float* W_in     = (const float*)d_in[3];
    const float* b_in     = (const float*)d_in[4];
    const float* W_out    = (const float*)d_in[5];
    const float* b_out    = (const float*)d_in[6];
    float* out = (float*)d_out;

    float *p_proj = nullptr, *p_attn = nullptr;
    cudaGetSymbolAddress((void**)&p_proj, g_proj);
    cudaGetSymbolAddress((void**)&p_attn, g_attn);

    cudaFuncSetAttribute(attn_kernel, cudaFuncAttributeMaxDynamicSharedMemorySize, SMEM_ATTN);

    // 1) proj = v_inv @ W_in^T + b_in      [4096 x 256]
    {
        dim3 grid(Dc / 64, (Bc * NKV) / 128);
        gemm_bias_kernel<<<grid, 512>>>(v_inv, W_in, b_in, p_proj, Bc * NKV, Dc, Dc);
    }
    // 2) fused attention -> g_attn         [4096 x 256]
    {
        dim3 grid(NQ / 32, Bc);
        attn_kernel<<<grid, 512, SMEM_ATTN>>>(messages, adjm, p_attn);
    }
    // 3) out = g_attn @ W_out^T + b_out
    {
        dim3 grid(Dc / 64, (Bc * NQ) / 128);
        gemm_bias_kernel<<<grid, 512>>>(p_attn, W_out, b_out, out, Bc * NQ, Dc, Dc);
    }
}